// round 11
// baseline (speedup 1.0000x reference)
#include <cuda_runtime.h>
#include <math.h>

#define B_ 64
#define S_ 4096
#define H_ 512
#define A_ 256
#define IN_ 256
#define NCHUNK 64
#define CHUNK (S_ / NCHUNK)            // 64 rows per chunk
#define WARPS_B 8
#define ROWS_PER_WARP (CHUNK / WARPS_B) // 8

#define QT_BLOCKS ((B_ * H_) / WARPS_B)   // 4096 blocks for qt
#define TR_BLOCKS ((A_ / 32) * (H_ / 32)) // 128 blocks for Wv transpose

// Scratch (no allocations allowed) ------------------------------------------
__device__ float g_Q[B_ * A_];             // Q = x@Wq + bq
__device__ float g_qt[B_ * H_];            // folded query  q~ = Q @ Wk^T
__device__ float g_cst[B_];                // Q . bk
__device__ float g_pm[B_ * NCHUNK];        // per-chunk running max
__device__ float g_pl[B_ * NCHUNK];        // per-chunk exp-sum
__device__ float g_pc[B_ * NCHUNK * H_];   // per-chunk weighted hidden sum (8 MB)
__device__ float g_part[4 * B_ * H_];      // c-quarter partial contexts (normalized)
__device__ float g_WvT[A_ * H_];           // transposed Wv (A-major)

// ---------------------------------------------------------------------------
// Kernel A1 (fused): blocks [0, 64): Q = x@Wq + bq and cst[b] = Q[b].bk
//                    blocks [64, 64+TR_BLOCKS): Wv transpose -> g_WvT
__global__ __launch_bounds__(256) void qwv_kernel(
    const float* __restrict__ x, const float* __restrict__ Wq,
    const float* __restrict__ bq, const float* __restrict__ bk,
    const float* __restrict__ Wv)
{
    if (blockIdx.x < B_) {
        const int b = blockIdx.x;
        const int a = threadIdx.x;
        __shared__ float shP[A_];

        const float* xr = x + b * IN_;
        float acc[8];
        #pragma unroll
        for (int k = 0; k < 8; ++k) acc[k] = 0.f;

        #pragma unroll 4
        for (int i = 0; i < IN_; i += 8) {
            #pragma unroll
            for (int k = 0; k < 8; ++k)
                acc[k] = fmaf(xr[i + k], Wq[(i + k) * A_ + a], acc[k]);
        }
        float q = 0.f;
        #pragma unroll
        for (int k = 0; k < 8; ++k) q += acc[k];
        q += bq[a];

        g_Q[b * A_ + a] = q;
        shP[a] = q * bk[a];
        __syncthreads();

        for (int s = 128; s > 0; s >>= 1) {
            if (a < s) shP[a] += shP[a + s];
            __syncthreads();
        }
        if (a == 0) g_cst[b] = shP[0];
    } else {
        // ---- Wv transpose: 32x32 tile per block ----
        __shared__ float tile[32][33];
        const int bx = blockIdx.x - B_;        // 0..127
        const int a0 = (bx & 7) * 32;
        const int h0 = (bx >> 3) * 32;
        const int tx = threadIdx.x & 31;
        const int ty = threadIdx.x >> 5;       // 0..7

        #pragma unroll
        for (int i = 0; i < 4; ++i) {
            const int h = h0 + ty + i * 8;
            tile[ty + i * 8][tx] = Wv[h * A_ + a0 + tx];
        }
        __syncthreads();
        #pragma unroll
        for (int i = 0; i < 4; ++i) {
            const int a = a0 + ty + i * 8;
            g_WvT[a * H_ + h0 + tx] = tile[tx][ty + i * 8];
        }
    }
}

// ---------------------------------------------------------------------------
// Kernel A2: q~[b,h] = sum_a Q[b,a] * Wk[h,a]  — one WARP per output element.
// grid = 4096, block = 256 (8 warps). Fully coalesced Wk/Q reads.
__global__ __launch_bounds__(256) void qt_kernel(const float* __restrict__ Wk)
{
    const int gw   = blockIdx.x * WARPS_B + (threadIdx.x >> 5); // 0..32767
    const int lane = threadIdx.x & 31;
    const int b = gw >> 9;          // /512
    const int h = gw & (H_ - 1);    // %512

    const float* wr = Wk + h * A_;
    const float* qr = g_Q + b * A_;
    float acc = 0.f;
    #pragma unroll
    for (int j = 0; j < A_ / 32; ++j) {
        const int a = j * 32 + lane;
        acc = fmaf(qr[a], wr[a], acc);
    }
    #pragma unroll
    for (int o = 16; o > 0; o >>= 1)
        acc += __shfl_xor_sync(0xffffffffu, acc, o);
    if (lane == 0) g_qt[b * H_ + h] = acc;
}

// ---------------------------------------------------------------------------
// Kernel B: streaming online-softmax pass over history_h.
// EXACT R5 configuration (measured 86.4us @ 80% DRAM): grid = (64, 64) = 4096
// CTAs, block = 256 (8 warps, 8 rows each), register q, pipelined row loads.
__global__ __launch_bounds__(256) void attn_pass_kernel(const float* __restrict__ hist)
{
    const int b     = blockIdx.y;
    const int chunk = blockIdx.x;
    const int tid   = threadIdx.x;
    const int w     = tid >> 5;
    const int lane  = tid & 31;

    float4 q4[4];
    const float4* qv = (const float4*)(g_qt + b * H_);
    #pragma unroll
    for (int j = 0; j < 4; ++j) q4[j] = qv[j * 32 + lane];

    const float cb = g_cst[b];
    const float inv_scale = 0.0625f; // 1/sqrt(256)

    float m = -INFINITY, l = 0.f;
    float4 acc[4];
    #pragma unroll
    for (int j = 0; j < 4; ++j) acc[j] = make_float4(0.f, 0.f, 0.f, 0.f);

    const int s0 = chunk * CHUNK + w * ROWS_PER_WARP;
    const float4* rowp = (const float4*)(hist + ((size_t)b * S_ + s0) * H_);
    const int row_stride4 = H_ / 4;

    float4 h4[4], n4[4];
    #pragma unroll
    for (int j = 0; j < 4; ++j) h4[j] = rowp[j * 32 + lane];

    #pragma unroll
    for (int r = 0; r < ROWS_PER_WARP; ++r) {
        if (r < ROWS_PER_WARP - 1) {
            const float4* np = rowp + (size_t)(r + 1) * row_stride4;
            #pragma unroll
            for (int j = 0; j < 4; ++j) n4[j] = np[j * 32 + lane];
        }

        float dot = 0.f;
        #pragma unroll
        for (int j = 0; j < 4; ++j) {
            dot = fmaf(h4[j].x, q4[j].x, dot);
            dot = fmaf(h4[j].y, q4[j].y, dot);
            dot = fmaf(h4[j].z, q4[j].z, dot);
            dot = fmaf(h4[j].w, q4[j].w, dot);
        }
        #pragma unroll
        for (int o = 16; o > 0; o >>= 1)
            dot += __shfl_xor_sync(0xffffffffu, dot, o);

        const float score = (dot + cb) * inv_scale;

        if (score > m) {                     // warp-uniform
            const float rsc = __expf(m - score);
            l *= rsc;
            #pragma unroll
            for (int j = 0; j < 4; ++j) {
                acc[j].x *= rsc; acc[j].y *= rsc; acc[j].z *= rsc; acc[j].w *= rsc;
            }
            m = score;
        }
        const float wgt = __expf(score - m);
        l += wgt;
        #pragma unroll
        for (int j = 0; j < 4; ++j) {
            acc[j].x = fmaf(wgt, h4[j].x, acc[j].x);
            acc[j].y = fmaf(wgt, h4[j].y, acc[j].y);
            acc[j].z = fmaf(wgt, h4[j].z, acc[j].z);
            acc[j].w = fmaf(wgt, h4[j].w, acc[j].w);
        }

        #pragma unroll
        for (int j = 0; j < 4; ++j) h4[j] = n4[j];
    }

    // ---- deterministic block combine ----
    __shared__ float s_m[WARPS_B], s_l[WARPS_B], s_scale[WARPS_B];
    __shared__ float s_c[WARPS_B][H_];   // 16 KB
    if (lane == 0) { s_m[w] = m; s_l[w] = l; }
    __syncthreads();
    if (tid == 0) {
        float mb = s_m[0];
        #pragma unroll
        for (int i = 1; i < WARPS_B; ++i) mb = fmaxf(mb, s_m[i]);
        float lb = 0.f;
        #pragma unroll
        for (int i = 0; i < WARPS_B; ++i) {
            const float sc_ = __expf(s_m[i] - mb);
            s_scale[i] = sc_;
            lb = fmaf(sc_, s_l[i], lb);
        }
        const int idx = b * NCHUNK + chunk;
        g_pm[idx] = mb;
        g_pl[idx] = lb;
    }
    __syncthreads();

    const float sc_w = s_scale[w];
    #pragma unroll
    for (int j = 0; j < 4; ++j) {
        float4 v = acc[j];
        v.x *= sc_w; v.y *= sc_w; v.z *= sc_w; v.w *= sc_w;
        ((float4*)&s_c[w][j * 128])[lane] = v;
    }
    __syncthreads();

    float* gout = g_pc + (size_t)(b * NCHUNK + chunk) * H_;
    for (int hh = tid; hh < H_; hh += 256) {
        float t = 0.f;
        #pragma unroll
        for (int wi = 0; wi < WARPS_B; ++wi) t += s_c[wi][hh];
        gout[hh] = t;
    }
}

// ---------------------------------------------------------------------------
// Kernel C1: partial combine over a 16-chunk quarter, normalized.
// grid = B_*2*4 = 512 blocks, block = 256. (R10-measured 6.4us.)
__global__ __launch_bounds__(256) void combine_part_kernel()
{
    const int idx = blockIdx.x;
    const int b  = idx >> 3;
    const int hs = (idx >> 2) & 1;
    const int cq = idx & 3;
    const int h  = hs * 256 + threadIdx.x;

    __shared__ float s_scale[16];

    if (threadIdx.x < 32) {
        const int lane = threadIdx.x;
        const float m0 = g_pm[b * NCHUNK + lane];
        const float m1 = g_pm[b * NCHUNK + lane + 32];
        const float l0 = g_pl[b * NCHUNK + lane];
        const float l1 = g_pl[b * NCHUNK + lane + 32];
        float mm = fmaxf(m0, m1);
        #pragma unroll
        for (int o = 16; o > 0; o >>= 1)
            mm = fmaxf(mm, __shfl_xor_sync(0xffffffffu, mm, o));
        float ls = fmaf(__expf(m0 - mm), l0, __expf(m1 - mm) * l1);
        #pragma unroll
        for (int o = 16; o > 0; o >>= 1)
            ls += __shfl_xor_sync(0xffffffffu, ls, o);
        const float invl = 1.0f / ls;
        if (lane < 16) {
            const int c = cq * 16 + lane;
            s_scale[lane] = __expf(g_pm[b * NCHUNK + c] - mm) * invl;
        }
    }
    __syncthreads();

    const float* base = g_pc + ((size_t)b * NCHUNK + cq * 16) * H_ + h;
    float t = 0.f;
    #pragma unroll
    for (int c = 0; c < 16; ++c)
        t = fmaf(s_scale[c], base[(size_t)c * H_], t);
    g_part[(size_t)cq * (B_ * H_) + b * H_ + h] = t;
}

// ---------------------------------------------------------------------------
// Kernel C2 (fused add + GEMV): out[b,a] = (sum of 4 quarter partials) . WvT[a]
// + bv[a] — one WARP per output. grid = 2048, block = 256. L2-hot reads.
__global__ __launch_bounds__(256) void out_kernel(
    const float* __restrict__ bv, float* __restrict__ out)
{
    const int gw   = blockIdx.x * WARPS_B + (threadIdx.x >> 5);
    const int lane = threadIdx.x & 31;
    const int b = gw >> 8;          // /256
    const int a = gw & (A_ - 1);    // %256

    const float* p0 = g_part + b * H_;
    const float* p1 = p0 + (size_t)(B_ * H_);
    const float* p2 = p0 + 2 * (size_t)(B_ * H_);
    const float* p3 = p0 + 3 * (size_t)(B_ * H_);
    const float* wr = g_WvT + a * H_;

    float acc = 0.f;
    #pragma unroll
    for (int j = 0; j < H_ / 32; ++j) {
        const int h = j * 32 + lane;
        const float ctxh = (p0[h] + p1[h]) + (p2[h] + p3[h]);
        acc = fmaf(ctxh, wr[h], acc);
    }
    #pragma unroll
    for (int o = 16; o > 0; o >>= 1)
        acc += __shfl_xor_sync(0xffffffffu, acc, o);
    if (lane == 0) out[b * A_ + a] = acc + bv[a];
}

// ---------------------------------------------------------------------------
extern "C" void kernel_launch(void* const* d_in, const int* in_sizes, int n_in,
                              void* d_out, int out_size)
{
    const float* x    = (const float*)d_in[0];
    const float* hist = (const float*)d_in[1];
    const float* Wq   = (const float*)d_in[2];
    const float* bq   = (const float*)d_in[3];
    const float* Wk   = (const float*)d_in[4];
    const float* bk   = (const float*)d_in[5];
    const float* Wv   = (const float*)d_in[6];
    const float* bv   = (const float*)d_in[7];
    float* out = (float*)d_out;

    qwv_kernel<<<B_ + TR_BLOCKS, 256>>>(x, Wq, bq, bk, Wv);
    qt_kernel<<<QT_BLOCKS, 256>>>(Wk);
    attn_pass_kernel<<<dim3(NCHUNK, B_), 256>>>(hist);
    combine_part_kernel<<<B_ * 8, 256>>>();
    out_kernel<<<(B_ * A_) / WARPS_B, 256>>>(bv, out);
}

// round 12
// speedup vs baseline: 1.0428x; 1.0428x over previous
#include <cuda_runtime.h>
#include <math.h>

#define B_ 64
#define S_ 4096
#define H_ 512
#define A_ 256
#define IN_ 256
#define NCHUNK 64
#define CHUNK (S_ / NCHUNK)            // 64 rows per chunk
#define WARPS_B 8
#define ROWS_PER_WARP (CHUNK / WARPS_B) // 8

#define QT_BLOCKS ((B_ * H_) / WARPS_B)   // 4096 blocks for qt
#define TR_BLOCKS ((A_ / 32) * (H_ / 32)) // 128 blocks for Wv transpose

// Scratch (no allocations allowed) ------------------------------------------
__device__ float g_Q[B_ * A_];             // Q = x@Wq + bq
__device__ float g_qt[B_ * H_];            // folded query  q~ = Q @ Wk^T
__device__ float g_cst[B_];                // Q . bk
__device__ float g_pm[B_ * NCHUNK];        // per-chunk running max
__device__ float g_pl[B_ * NCHUNK];        // per-chunk exp-sum
__device__ float g_pc[B_ * NCHUNK * H_];   // per-chunk weighted hidden sum (8 MB)
__device__ float g_part[4 * B_ * H_];      // c-quarter partial contexts (normalized)
__device__ float g_WvT[A_ * H_];           // transposed Wv (A-major)

// ---------------------------------------------------------------------------
// Kernel A1: Q = x@Wq + bq  and  cst[b] = Q[b] . bk   (8 chains, modest unroll)
// (EXACT R9 version)
__global__ __launch_bounds__(256) void q_kernel(
    const float* __restrict__ x, const float* __restrict__ Wq,
    const float* __restrict__ bq, const float* __restrict__ bk)
{
    const int b = blockIdx.x;
    const int a = threadIdx.x;
    __shared__ float shP[A_];

    const float* xr = x + b * IN_;
    float acc[8];
    #pragma unroll
    for (int k = 0; k < 8; ++k) acc[k] = 0.f;

    #pragma unroll 4
    for (int i = 0; i < IN_; i += 8) {
        #pragma unroll
        for (int k = 0; k < 8; ++k)
            acc[k] = fmaf(xr[i + k], Wq[(i + k) * A_ + a], acc[k]);
    }
    float q = 0.f;
    #pragma unroll
    for (int k = 0; k < 8; ++k) q += acc[k];
    q += bq[a];

    g_Q[b * A_ + a] = q;
    shP[a] = q * bk[a];
    __syncthreads();

    for (int s = 128; s > 0; s >>= 1) {
        if (a < s) shP[a] += shP[a + s];
        __syncthreads();
    }
    if (a == 0) g_cst[b] = shP[0];
}

// ---------------------------------------------------------------------------
// Kernel A2 (fused, EXACT R9 version): blocks [0, QT_BLOCKS) compute q~;
// blocks [QT_BLOCKS, QT_BLOCKS+TR_BLOCKS) transpose Wv.
__global__ __launch_bounds__(256) void prep_kernel(
    const float* __restrict__ Wk, const float* __restrict__ Wv)
{
    if (blockIdx.x < QT_BLOCKS) {
        const int gw   = blockIdx.x * WARPS_B + (threadIdx.x >> 5); // 0..32767
        const int lane = threadIdx.x & 31;
        const int b = gw >> 9;          // /512
        const int h = gw & (H_ - 1);    // %512

        const float* wr = Wk + h * A_;
        const float* qr = g_Q + b * A_;
        float acc = 0.f;
        #pragma unroll
        for (int j = 0; j < A_ / 32; ++j) {
            const int a = j * 32 + lane;
            acc = fmaf(qr[a], wr[a], acc);
        }
        #pragma unroll
        for (int o = 16; o > 0; o >>= 1)
            acc += __shfl_xor_sync(0xffffffffu, acc, o);
        if (lane == 0) g_qt[b * H_ + h] = acc;
    } else {
        __shared__ float tile[32][33];
        const int bx = blockIdx.x - QT_BLOCKS; // 0..127
        const int a0 = (bx & 7) * 32;
        const int h0 = (bx >> 3) * 32;
        const int tx = threadIdx.x & 31;
        const int ty = threadIdx.x >> 5;       // 0..7

        #pragma unroll
        for (int i = 0; i < 4; ++i) {
            const int h = h0 + ty + i * 8;
            tile[ty + i * 8][tx] = Wv[h * A_ + a0 + tx];
        }
        __syncthreads();
        #pragma unroll
        for (int i = 0; i < 4; ++i) {
            const int a = a0 + ty + i * 8;
            g_WvT[a * H_ + h0 + tx] = tile[tx][ty + i * 8];
        }
    }
}

// ---------------------------------------------------------------------------
// Kernel B: streaming online-softmax pass over history_h. (EXACT R9 version:
// grid = (64,64) = 4096 CTAs, 8 warps x 8 rows, register q, pipelined loads.)
__global__ __launch_bounds__(256) void attn_pass_kernel(const float* __restrict__ hist)
{
    const int b     = blockIdx.y;
    const int chunk = blockIdx.x;
    const int tid   = threadIdx.x;
    const int w     = tid >> 5;
    const int lane  = tid & 31;

    float4 q4[4];
    const float4* qv = (const float4*)(g_qt + b * H_);
    #pragma unroll
    for (int j = 0; j < 4; ++j) q4[j] = qv[j * 32 + lane];

    const float cb = g_cst[b];
    const float inv_scale = 0.0625f; // 1/sqrt(256)

    float m = -INFINITY, l = 0.f;
    float4 acc[4];
    #pragma unroll
    for (int j = 0; j < 4; ++j) acc[j] = make_float4(0.f, 0.f, 0.f, 0.f);

    const int s0 = chunk * CHUNK + w * ROWS_PER_WARP;
    const float4* rowp = (const float4*)(hist + ((size_t)b * S_ + s0) * H_);
    const int row_stride4 = H_ / 4;

    float4 h4[4], n4[4];
    #pragma unroll
    for (int j = 0; j < 4; ++j) h4[j] = rowp[j * 32 + lane];

    #pragma unroll
    for (int r = 0; r < ROWS_PER_WARP; ++r) {
        if (r < ROWS_PER_WARP - 1) {
            const float4* np = rowp + (size_t)(r + 1) * row_stride4;
            #pragma unroll
            for (int j = 0; j < 4; ++j) n4[j] = np[j * 32 + lane];
        }

        float dot = 0.f;
        #pragma unroll
        for (int j = 0; j < 4; ++j) {
            dot = fmaf(h4[j].x, q4[j].x, dot);
            dot = fmaf(h4[j].y, q4[j].y, dot);
            dot = fmaf(h4[j].z, q4[j].z, dot);
            dot = fmaf(h4[j].w, q4[j].w, dot);
        }
        #pragma unroll
        for (int o = 16; o > 0; o >>= 1)
            dot += __shfl_xor_sync(0xffffffffu, dot, o);

        const float score = (dot + cb) * inv_scale;

        if (score > m) {                     // warp-uniform
            const float rsc = __expf(m - score);
            l *= rsc;
            #pragma unroll
            for (int j = 0; j < 4; ++j) {
                acc[j].x *= rsc; acc[j].y *= rsc; acc[j].z *= rsc; acc[j].w *= rsc;
            }
            m = score;
        }
        const float wgt = __expf(score - m);
        l += wgt;
        #pragma unroll
        for (int j = 0; j < 4; ++j) {
            acc[j].x = fmaf(wgt, h4[j].x, acc[j].x);
            acc[j].y = fmaf(wgt, h4[j].y, acc[j].y);
            acc[j].z = fmaf(wgt, h4[j].z, acc[j].z);
            acc[j].w = fmaf(wgt, h4[j].w, acc[j].w);
        }

        #pragma unroll
        for (int j = 0; j < 4; ++j) h4[j] = n4[j];
    }

    // ---- deterministic block combine ----
    __shared__ float s_m[WARPS_B], s_l[WARPS_B], s_scale[WARPS_B];
    __shared__ float s_c[WARPS_B][H_];   // 16 KB
    if (lane == 0) { s_m[w] = m; s_l[w] = l; }
    __syncthreads();
    if (tid == 0) {
        float mb = s_m[0];
        #pragma unroll
        for (int i = 1; i < WARPS_B; ++i) mb = fmaxf(mb, s_m[i]);
        float lb = 0.f;
        #pragma unroll
        for (int i = 0; i < WARPS_B; ++i) {
            const float sc_ = __expf(s_m[i] - mb);
            s_scale[i] = sc_;
            lb = fmaf(sc_, s_l[i], lb);
        }
        const int idx = b * NCHUNK + chunk;
        g_pm[idx] = mb;
        g_pl[idx] = lb;
    }
    __syncthreads();

    const float sc_w = s_scale[w];
    #pragma unroll
    for (int j = 0; j < 4; ++j) {
        float4 v = acc[j];
        v.x *= sc_w; v.y *= sc_w; v.z *= sc_w; v.w *= sc_w;
        ((float4*)&s_c[w][j * 128])[lane] = v;
    }
    __syncthreads();

    float* gout = g_pc + (size_t)(b * NCHUNK + chunk) * H_;
    for (int hh = tid; hh < H_; hh += 256) {
        float t = 0.f;
        #pragma unroll
        for (int wi = 0; wi < WARPS_B; ++wi) t += s_c[wi][hh];
        gout[hh] = t;
    }
}

// ---------------------------------------------------------------------------
// Kernel C1: partial combine over a 16-chunk quarter, normalized.
// grid = 512 blocks, block = 256. (R10/R11-measured 6.4us.)
__global__ __launch_bounds__(256) void combine_part_kernel()
{
    const int idx = blockIdx.x;
    const int b  = idx >> 3;
    const int hs = (idx >> 2) & 1;
    const int cq = idx & 3;
    const int h  = hs * 256 + threadIdx.x;

    __shared__ float s_scale[16];

    if (threadIdx.x < 32) {
        const int lane = threadIdx.x;
        const float m0 = g_pm[b * NCHUNK + lane];
        const float m1 = g_pm[b * NCHUNK + lane + 32];
        const float l0 = g_pl[b * NCHUNK + lane];
        const float l1 = g_pl[b * NCHUNK + lane + 32];
        float mm = fmaxf(m0, m1);
        #pragma unroll
        for (int o = 16; o > 0; o >>= 1)
            mm = fmaxf(mm, __shfl_xor_sync(0xffffffffu, mm, o));
        float ls = fmaf(__expf(m0 - mm), l0, __expf(m1 - mm) * l1);
        #pragma unroll
        for (int o = 16; o > 0; o >>= 1)
            ls += __shfl_xor_sync(0xffffffffu, ls, o);
        const float invl = 1.0f / ls;
        if (lane < 16) {
            const int c = cq * 16 + lane;
            s_scale[lane] = __expf(g_pm[b * NCHUNK + c] - mm) * invl;
        }
    }
    __syncthreads();

    const float* base = g_pc + ((size_t)b * NCHUNK + cq * 16) * H_ + h;
    float t = 0.f;
    #pragma unroll
    for (int c = 0; c < 16; ++c)
        t = fmaf(s_scale[c], base[(size_t)c * H_], t);
    g_part[(size_t)cq * (B_ * H_) + b * H_ + h] = t;
}

// ---------------------------------------------------------------------------
// Kernel C2 (fused add + GEMV): out[b,a] = (sum of 4 quarter partials) . WvT[a]
// + bv[a] — one WARP per output. grid = 2048, block = 256. L2-hot reads.
__global__ __launch_bounds__(256) void out_kernel(
    const float* __restrict__ bv, float* __restrict__ out)
{
    const int gw   = blockIdx.x * WARPS_B + (threadIdx.x >> 5);
    const int lane = threadIdx.x & 31;
    const int b = gw >> 8;          // /256
    const int a = gw & (A_ - 1);    // %256

    const float* p0 = g_part + b * H_;
    const float* p1 = p0 + (size_t)(B_ * H_);
    const float* p2 = p0 + 2 * (size_t)(B_ * H_);
    const float* p3 = p0 + 3 * (size_t)(B_ * H_);
    const float* wr = g_WvT + a * H_;

    float acc = 0.f;
    #pragma unroll
    for (int j = 0; j < H_ / 32; ++j) {
        const int h = j * 32 + lane;
        const float ctxh = (p0[h] + p1[h]) + (p2[h] + p3[h]);
        acc = fmaf(ctxh, wr[h], acc);
    }
    #pragma unroll
    for (int o = 16; o > 0; o >>= 1)
        acc += __shfl_xor_sync(0xffffffffu, acc, o);
    if (lane == 0) out[b * A_ + a] = acc + bv[a];
}

// ---------------------------------------------------------------------------
extern "C" void kernel_launch(void* const* d_in, const int* in_sizes, int n_in,
                              void* d_out, int out_size)
{
    const float* x    = (const float*)d_in[0];
    const float* hist = (const float*)d_in[1];
    const float* Wq   = (const float*)d_in[2];
    const float* bq   = (const float*)d_in[3];
    const float* Wk   = (const float*)d_in[4];
    const float* bk   = (const float*)d_in[5];
    const float* Wv   = (const float*)d_in[6];
    const float* bv   = (const float*)d_in[7];
    float* out = (float*)d_out;

    q_kernel<<<B_, 256>>>(x, Wq, bq, bk);
    prep_kernel<<<QT_BLOCKS + TR_BLOCKS, 256>>>(Wk, Wv);
    attn_pass_kernel<<<dim3(NCHUNK, B_), 256>>>(hist);
    combine_part_kernel<<<B_ * 8, 256>>>();
    out_kernel<<<(B_ * A_) / WARPS_B, 256>>>(bv, out);
}